// round 3
// baseline (speedup 1.0000x reference)
#include <cuda_runtime.h>
#include <cuda_bf16.h>

// Problem dims (fixed by the reference)
#define EDIM 1024
#define RDIM 16
#define BATCH 4
#define SLEN 2048
#define MTOT (BATCH * SLEN)   // 8192

// ---------------- device scratch (no allocations allowed) ----------------
// weff[0]=Q, weff[1]=K, weff[2]=V effective weights
__device__ float g_weff[3][EDIM * EDIM];
__device__ float g_q[(size_t)MTOT * EDIM];
__device__ float g_k[(size_t)MTOT * EDIM];
__device__ float g_v[(size_t)MTOT * EDIM];
__device__ float g_scores[(size_t)BATCH * SLEN * SLEN];
__device__ float g_ctx[(size_t)MTOT * EDIM];

// ---- fold LoRA into base weights: Weff[f][e] = W[f][e] + sum_r B[f][r]*A[r][e]
// grid.z selects which of the 3 projections; W/B/A pointers passed per-slot.
__global__ void fold_lora_kernel(const float* __restrict__ W0,
                                 const float* __restrict__ B0,
                                 const float* __restrict__ A0,
                                 const float* __restrict__ W1,
                                 const float* __restrict__ B1,
                                 const float* __restrict__ A1,
                                 const float* __restrict__ W2,
                                 const float* __restrict__ B2,
                                 const float* __restrict__ A2,
                                 float* __restrict__ Weff) {
    const float* W;
    const float* Bm;
    const float* Am;
    if (blockIdx.z == 0)      { W = W0; Bm = B0; Am = A0; }
    else if (blockIdx.z == 1) { W = W1; Bm = B1; Am = A1; }
    else                      { W = W2; Bm = B2; Am = A2; }
    float* dst = Weff + (size_t)blockIdx.z * EDIM * EDIM;

    int idx = blockIdx.x * blockDim.x + threadIdx.x;   // over E*E
    int f = idx >> 10;
    int e = idx & (EDIM - 1);
    float acc = W[idx];
#pragma unroll
    for (int r = 0; r < RDIM; r++)
        acc += Bm[f * RDIM + r] * Am[r * EDIM + e];
    dst[idx] = acc;
}

// ---------------- tiled fp32 GEMM, 128x128x16, 256 threads, 8x8 microtile ----
#define BM 128
#define BN 128
#define BK 16
#define PAD 4

// C[m][n] = alpha * sum_k A[m][k] * B[n][k]   (both K-contiguous, "NT")
__global__ __launch_bounds__(256, 2) void gemm_nt_kernel(
    const float* __restrict__ A, const float* __restrict__ B,
    float* __restrict__ C, int Mdim, int Ndim, int Kdim, float alpha,
    long sA, long sB, long sC) {
    __shared__ __align__(16) float As[BK][BM + PAD];
    __shared__ __align__(16) float Bs[BK][BN + PAD];
    A += (size_t)blockIdx.z * sA;
    B += (size_t)blockIdx.z * sB;
    C += (size_t)blockIdx.z * sC;
    const int tid = threadIdx.x;
    const int row0 = blockIdx.y * BM;
    const int col0 = blockIdx.x * BN;
    const int ty = tid >> 4, tx = tid & 15;

    float acc[8][8];
#pragma unroll
    for (int i = 0; i < 8; i++)
#pragma unroll
        for (int j = 0; j < 8; j++) acc[i][j] = 0.f;

    for (int k0 = 0; k0 < Kdim; k0 += BK) {
        // A tile: BM rows x BK (K-contig), store transposed
#pragma unroll
        for (int l = 0; l < 2; l++) {
            int i = tid + l * 256;           // 512 float4 total
            int r = i >> 2;                  // 0..127
            int kq = (i & 3) << 2;           // 0,4,8,12
            float4 val = *reinterpret_cast<const float4*>(
                &A[(size_t)(row0 + r) * Kdim + k0 + kq]);
            As[kq + 0][r] = val.x; As[kq + 1][r] = val.y;
            As[kq + 2][r] = val.z; As[kq + 3][r] = val.w;
        }
        // B tile: BN rows x BK (K-contig), store transposed
#pragma unroll
        for (int l = 0; l < 2; l++) {
            int i = tid + l * 256;
            int c = i >> 2;
            int kq = (i & 3) << 2;
            float4 val = *reinterpret_cast<const float4*>(
                &B[(size_t)(col0 + c) * Kdim + k0 + kq]);
            Bs[kq + 0][c] = val.x; Bs[kq + 1][c] = val.y;
            Bs[kq + 2][c] = val.z; Bs[kq + 3][c] = val.w;
        }
        __syncthreads();
#pragma unroll
        for (int k = 0; k < BK; k++) {
            float a[8], b[8];
            *(float4*)&a[0] = *(float4*)&As[k][ty * 8];
            *(float4*)&a[4] = *(float4*)&As[k][ty * 8 + 4];
            *(float4*)&b[0] = *(float4*)&Bs[k][tx * 8];
            *(float4*)&b[4] = *(float4*)&Bs[k][tx * 8 + 4];
#pragma unroll
            for (int i = 0; i < 8; i++)
#pragma unroll
                for (int j = 0; j < 8; j++) acc[i][j] += a[i] * b[j];
        }
        __syncthreads();
    }
#pragma unroll
    for (int i = 0; i < 8; i++) {
        size_t off = (size_t)(row0 + ty * 8 + i) * Ndim + col0 + tx * 8;
        float4 o0 = make_float4(acc[i][0] * alpha, acc[i][1] * alpha,
                                acc[i][2] * alpha, acc[i][3] * alpha);
        float4 o1 = make_float4(acc[i][4] * alpha, acc[i][5] * alpha,
                                acc[i][6] * alpha, acc[i][7] * alpha);
        *reinterpret_cast<float4*>(&C[off]) = o0;
        *reinterpret_cast<float4*>(&C[off + 4]) = o1;
    }
}

// C[m][n] = alpha * sum_k A[m][k] * B[k][n]   (A K-contig, B N-contig, "NN")
__global__ __launch_bounds__(256, 2) void gemm_nn_kernel(
    const float* __restrict__ A, const float* __restrict__ B,
    float* __restrict__ C, int Mdim, int Ndim, int Kdim, float alpha,
    long sA, long sB, long sC) {
    __shared__ __align__(16) float As[BK][BM + PAD];
    __shared__ __align__(16) float Bs[BK][BN + PAD];
    A += (size_t)blockIdx.z * sA;
    B += (size_t)blockIdx.z * sB;
    C += (size_t)blockIdx.z * sC;
    const int tid = threadIdx.x;
    const int row0 = blockIdx.y * BM;
    const int col0 = blockIdx.x * BN;
    const int ty = tid >> 4, tx = tid & 15;

    float acc[8][8];
#pragma unroll
    for (int i = 0; i < 8; i++)
#pragma unroll
        for (int j = 0; j < 8; j++) acc[i][j] = 0.f;

    for (int k0 = 0; k0 < Kdim; k0 += BK) {
        // A tile: transposed store (same as NT)
#pragma unroll
        for (int l = 0; l < 2; l++) {
            int i = tid + l * 256;
            int r = i >> 2;
            int kq = (i & 3) << 2;
            float4 val = *reinterpret_cast<const float4*>(
                &A[(size_t)(row0 + r) * Kdim + k0 + kq]);
            As[kq + 0][r] = val.x; As[kq + 1][r] = val.y;
            As[kq + 2][r] = val.z; As[kq + 3][r] = val.w;
        }
        // B tile: BK rows x BN, N-contiguous -> direct store
#pragma unroll
        for (int l = 0; l < 2; l++) {
            int i = tid + l * 256;           // 512 float4 = 16 rows x 32 float4
            int kr = i >> 5;                 // 0..15
            int nc = (i & 31) << 2;          // 0..124
            float4 val = *reinterpret_cast<const float4*>(
                &B[(size_t)(k0 + kr) * Ndim + col0 + nc]);
            *reinterpret_cast<float4*>(&Bs[kr][nc]) = val;
        }
        __syncthreads();
#pragma unroll
        for (int k = 0; k < BK; k++) {
            float a[8], b[8];
            *(float4*)&a[0] = *(float4*)&As[k][ty * 8];
            *(float4*)&a[4] = *(float4*)&As[k][ty * 8 + 4];
            *(float4*)&b[0] = *(float4*)&Bs[k][tx * 8];
            *(float4*)&b[4] = *(float4*)&Bs[k][tx * 8 + 4];
#pragma unroll
            for (int i = 0; i < 8; i++)
#pragma unroll
                for (int j = 0; j < 8; j++) acc[i][j] += a[i] * b[j];
        }
        __syncthreads();
    }
#pragma unroll
    for (int i = 0; i < 8; i++) {
        size_t off = (size_t)(row0 + ty * 8 + i) * Ndim + col0 + tx * 8;
        float4 o0 = make_float4(acc[i][0] * alpha, acc[i][1] * alpha,
                                acc[i][2] * alpha, acc[i][3] * alpha);
        float4 o1 = make_float4(acc[i][4] * alpha, acc[i][5] * alpha,
                                acc[i][6] * alpha, acc[i][7] * alpha);
        *reinterpret_cast<float4*>(&C[off]) = o0;
        *reinterpret_cast<float4*>(&C[off + 4]) = o1;
    }
}

// ---------------- row softmax (one block per row of length n=2048) --------
__global__ void softmax_rows_kernel(float* __restrict__ Sc, int n) {
    float* row = Sc + (size_t)blockIdx.x * n;
    __shared__ float red[256];
    const int t = threadIdx.x;

    float m = -3.4e38f;
    for (int i = t; i < n; i += 256) m = fmaxf(m, row[i]);
    red[t] = m;
    __syncthreads();
    for (int s = 128; s > 0; s >>= 1) {
        if (t < s) red[t] = fmaxf(red[t], red[t + s]);
        __syncthreads();
    }
    m = red[0];
    __syncthreads();

    float sum = 0.f;
    for (int i = t; i < n; i += 256) {
        float e = __expf(row[i] - m);
        row[i] = e;
        sum += e;
    }
    red[t] = sum;
    __syncthreads();
    for (int s = 128; s > 0; s >>= 1) {
        if (t < s) red[t] += red[t + s];
        __syncthreads();
    }
    float inv = 1.0f / red[0];
    __syncthreads();
    for (int i = t; i < n; i += 256) row[i] *= inv;
}

// --------------------------------------------------------------------------
extern "C" void kernel_launch(void* const* d_in, const int* in_sizes, int n_in,
                              void* d_out, int out_size) {
    const float* query = (const float*)d_in[0];
    const float* key_  = (const float*)d_in[1];
    const float* value = (const float*)d_in[2];
    const float* Qw = (const float*)d_in[3];
    const float* Kw = (const float*)d_in[4];
    const float* Vw = (const float*)d_in[5];
    const float* QA = (const float*)d_in[6];
    const float* QB = (const float*)d_in[7];
    const float* KA = (const float*)d_in[8];
    const float* KB = (const float*)d_in[9];
    const float* VA = (const float*)d_in[10];
    const float* VB = (const float*)d_in[11];
    const float* Ow = (const float*)d_in[12];
    float* out = (float*)d_out;

    float *weff, *q, *k, *v, *scores, *ctx;
    cudaGetSymbolAddress((void**)&weff, g_weff);
    cudaGetSymbolAddress((void**)&q, g_q);
    cudaGetSymbolAddress((void**)&k, g_k);
    cudaGetSymbolAddress((void**)&v, g_v);
    cudaGetSymbolAddress((void**)&scores, g_scores);
    cudaGetSymbolAddress((void**)&ctx, g_ctx);
    float* weff_q = weff;
    float* weff_k = weff + (size_t)EDIM * EDIM;
    float* weff_v = weff + (size_t)2 * EDIM * EDIM;

    // 1) fold LoRA into effective weights (one launch, grid.z = 3)
    dim3 gf(EDIM * EDIM / 256, 1, 3);
    fold_lora_kernel<<<gf, 256>>>(Qw, QB, QA, Kw, KB, KA, Vw, VB, VA, weff);

    // 2) Q/K/V projections: [8192,1024] @ Weff^T
    dim3 gp(EDIM / BN, MTOT / BM, 1);
    gemm_nt_kernel<<<gp, 256>>>(query, weff_q, q, MTOT, EDIM, EDIM, 1.f, 0, 0, 0);
    gemm_nt_kernel<<<gp, 256>>>(key_,  weff_k, k, MTOT, EDIM, EDIM, 1.f, 0, 0, 0);
    gemm_nt_kernel<<<gp, 256>>>(value, weff_v, v, MTOT, EDIM, EDIM, 1.f, 0, 0, 0);

    // 3) scores[b] = Q[b] @ K[b]^T / sqrt(E)
    dim3 gs(SLEN / BN, SLEN / BM, BATCH);
    gemm_nt_kernel<<<gs, 256>>>(q, k, scores, SLEN, SLEN, EDIM, 0.03125f,
                                (long)SLEN * EDIM, (long)SLEN * EDIM,
                                (long)SLEN * SLEN);

    // 4) row softmax
    softmax_rows_kernel<<<BATCH * SLEN, 256>>>(scores, SLEN);

    // 5) ctx[b] = attn[b] @ V[b]
    dim3 gc(EDIM / BN, SLEN / BM, BATCH);
    gemm_nn_kernel<<<gc, 256>>>(scores, v, ctx, SLEN, EDIM, SLEN, 1.f,
                                (long)SLEN * SLEN, (long)SLEN * EDIM,
                                (long)SLEN * EDIM);

    // 6) out = ctx @ O^T
    dim3 go(EDIM / BN, MTOT / BM, 1);
    gemm_nt_kernel<<<go, 256>>>(ctx, Ow, out, MTOT, EDIM, EDIM, 1.f, 0, 0, 0);
}

// round 7
// speedup vs baseline: 3.1544x; 3.1544x over previous
#include <cuda_runtime.h>
#include <cstdint>

// Problem dims (fixed by the reference)
#define EDIM 1024
#define RDIM 16
#define BATCH 4
#define SLEN 2048
#define MTOT (BATCH * SLEN)   // 8192

// ---------------- device scratch (no allocations allowed) ----------------
__device__ float g_weff[3][EDIM * EDIM];                 // Q,K,V effective weights
__device__ float g_q[(size_t)MTOT * EDIM];
__device__ float g_k[(size_t)MTOT * EDIM];
__device__ float g_vT[(size_t)EDIM * MTOT];              // V projection, transposed
__device__ float g_scores[(size_t)BATCH * SLEN * SLEN];
__device__ float g_ctx[(size_t)MTOT * EDIM];

// ---- fold LoRA: Weff[f][e] = W[f][e] + sum_r B[f][r]*A[r][e], grid.z picks proj
__global__ void fold_lora_kernel(const float* __restrict__ W0, const float* __restrict__ B0,
                                 const float* __restrict__ A0,
                                 const float* __restrict__ W1, const float* __restrict__ B1,
                                 const float* __restrict__ A1,
                                 const float* __restrict__ W2, const float* __restrict__ B2,
                                 const float* __restrict__ A2,
                                 float* __restrict__ Weff) {
    const float *W, *Bm, *Am;
    if (blockIdx.z == 0)      { W = W0; Bm = B0; Am = A0; }
    else if (blockIdx.z == 1) { W = W1; Bm = B1; Am = A1; }
    else                      { W = W2; Bm = B2; Am = A2; }
    float* dst = Weff + (size_t)blockIdx.z * EDIM * EDIM;
    int idx = blockIdx.x * blockDim.x + threadIdx.x;
    int f = idx >> 10;
    int e = idx & (EDIM - 1);
    float acc = W[idx];
#pragma unroll
    for (int r = 0; r < RDIM; r++) acc += Bm[f * RDIM + r] * Am[r * EDIM + e];
    dst[idx] = acc;
}

// ======== tf32 mma.sync NT GEMM: C[m][n] = alpha * sum_k A[m][k]*B[n][k] ========
// Block tile 128x128x32, 8 warps (2 x 4), warp tile 64x32, mma m16n8k8.
#define BM 128
#define BN 128
#define BK 32
#define SMSTRIDE 36                         // floats per row (32 + 4 pad)
#define TILE_F (128 * SMSTRIDE)             // floats per A (or B) stage tile
#define STAGE_F (2 * TILE_F)                // A + B
#define GEMM_SMEM (2 * STAGE_F * 4)         // 2 stages, bytes = 73728

__device__ __forceinline__ uint32_t f2tf(float f) {
    uint32_t u;
    asm("cvt.rna.tf32.f32 %0, %1;" : "=r"(u) : "f"(f));
    return u;
}

__device__ __forceinline__ void mma_tf32(float c[4], const uint32_t a[4], const uint32_t b[2]) {
    asm volatile(
        "mma.sync.aligned.m16n8k8.row.col.f32.tf32.tf32.f32 "
        "{%0,%1,%2,%3}, {%4,%5,%6,%7}, {%8,%9}, {%0,%1,%2,%3};"
        : "+f"(c[0]), "+f"(c[1]), "+f"(c[2]), "+f"(c[3])
        : "r"(a[0]), "r"(a[1]), "r"(a[2]), "r"(a[3]), "r"(b[0]), "r"(b[1]));
}

__global__ __launch_bounds__(256) void gemm_tc_kernel(
    const float* __restrict__ A, const float* __restrict__ B, float* __restrict__ C,
    int ldA, int ldB, int ldC, int Kdim, float alpha, int transC,
    long sA, long sB, long sC) {
    extern __shared__ __align__(16) float sm[];
    A += (size_t)blockIdx.z * sA + (size_t)blockIdx.y * BM * ldA;
    B += (size_t)blockIdx.z * sB + (size_t)blockIdx.x * BN * ldB;
    C += (size_t)blockIdx.z * sC;
    const int tid = threadIdx.x;
    const int wid = tid >> 5, lid = tid & 31;
    const int wm = wid & 1, wn = wid >> 1;      // warp grid 2 x 4
    const int mb = wm * 64, nb = wn * 32;
    const int g = lid >> 2, t = lid & 3;        // fragment row-group / lane-in-group

    float acc[4][4][4];
#pragma unroll
    for (int im = 0; im < 4; im++)
#pragma unroll
        for (int in = 0; in < 4; in++)
#pragma unroll
            for (int q = 0; q < 4; q++) acc[im][in][q] = 0.f;

    const int NT = Kdim / BK;

    // tile load: 128 rows x 8 float4 each for A and B; 256 thr -> 4+4 vectors/thr
#define LOAD_TILE(KT, S)                                                          \
    do {                                                                          \
        float* as = sm + (S) * STAGE_F;                                           \
        float* bs = as + TILE_F;                                                  \
        const float* Ag = A + (size_t)(KT) * BK;                                  \
        const float* Bg = B + (size_t)(KT) * BK;                                  \
        _Pragma("unroll")                                                         \
        for (int j = 0; j < 4; j++) {                                             \
            int idx = j * 256 + tid;                                              \
            int r = idx >> 3, q = idx & 7;                                        \
            uint32_t so;                                                          \
            asm("{ .reg .u64 u; cvta.to.shared.u64 u, %1; cvt.u32.u64 %0, u; }"   \
                : "=r"(so) : "l"(as + r * SMSTRIDE + q * 4));                     \
            asm volatile("cp.async.cg.shared.global [%0], [%1], 16;"              \
                         :: "r"(so), "l"(Ag + (size_t)r * ldA + q * 4));          \
        }                                                                         \
        _Pragma("unroll")                                                         \
        for (int j = 0; j < 4; j++) {                                             \
            int idx = j * 256 + tid;                                              \
            int r = idx >> 3, q = idx & 7;                                        \
            uint32_t so;                                                          \
            asm("{ .reg .u64 u; cvta.to.shared.u64 u, %1; cvt.u32.u64 %0, u; }"   \
                : "=r"(so) : "l"(bs + r * SMSTRIDE + q * 4));                     \
            asm volatile("cp.async.cg.shared.global [%0], [%1], 16;"              \
                         :: "r"(so), "l"(Bg + (size_t)r * ldB + q * 4));          \
        }                                                                         \
        asm volatile("cp.async.commit_group;" ::: "memory");                      \
    } while (0)

    LOAD_TILE(0, 0);
    if (NT > 1) LOAD_TILE(1, 1);

    for (int kt = 0; kt < NT; kt++) {
        if (kt + 1 < NT)
            asm volatile("cp.async.wait_group 1;" ::: "memory");
        else
            asm volatile("cp.async.wait_group 0;" ::: "memory");
        __syncthreads();

        const float* as = sm + (kt & 1) * STAGE_F;
        const float* bs = as + TILE_F;
#pragma unroll
        for (int ks = 0; ks < 4; ks++) {
            const int k0 = ks * 8;
            uint32_t ua[4][4];
#pragma unroll
            for (int im = 0; im < 4; im++) {
                const float* ap = as + (mb + im * 16 + g) * SMSTRIDE + k0 + t;
                ua[im][0] = f2tf(ap[0]);
                ua[im][1] = f2tf(ap[8 * SMSTRIDE]);
                ua[im][2] = f2tf(ap[4]);
                ua[im][3] = f2tf(ap[8 * SMSTRIDE + 4]);
            }
            uint32_t ub[4][2];
#pragma unroll
            for (int in = 0; in < 4; in++) {
                const float* bp = bs + (nb + in * 8 + g) * SMSTRIDE + k0 + t;
                ub[in][0] = f2tf(bp[0]);
                ub[in][1] = f2tf(bp[4]);
            }
#pragma unroll
            for (int im = 0; im < 4; im++)
#pragma unroll
                for (int in = 0; in < 4; in++) mma_tf32(acc[im][in], ua[im], ub[in]);
        }
        __syncthreads();
        if (kt + 2 < NT) LOAD_TILE(kt + 2, kt & 1);
    }

    // epilogue
#pragma unroll
    for (int im = 0; im < 4; im++) {
        const int row0 = blockIdx.y * BM + mb + im * 16 + g;
#pragma unroll
        for (int in = 0; in < 4; in++) {
            const int col = blockIdx.x * BN + nb + in * 8 + t * 2;
            float v0 = acc[im][in][0] * alpha, v1 = acc[im][in][1] * alpha;
            float v2 = acc[im][in][2] * alpha, v3 = acc[im][in][3] * alpha;
            if (!transC) {
                *reinterpret_cast<float2*>(&C[(size_t)row0 * ldC + col]) = make_float2(v0, v1);
                *reinterpret_cast<float2*>(&C[(size_t)(row0 + 8) * ldC + col]) = make_float2(v2, v3);
            } else {
                C[(size_t)col * ldC + row0] = v0;
                C[(size_t)(col + 1) * ldC + row0] = v1;
                C[(size_t)col * ldC + row0 + 8] = v2;
                C[(size_t)(col + 1) * ldC + row0 + 8] = v3;
            }
        }
    }
}

// ---------------- row softmax (one block per row of length n=2048) --------
__global__ void softmax_rows_kernel(float* __restrict__ Sc, int n) {
    float* row = Sc + (size_t)blockIdx.x * n;
    __shared__ float red[256];
    const int t = threadIdx.x;

    float m = -3.4e38f;
    for (int i = t; i < n; i += 256) m = fmaxf(m, row[i]);
    red[t] = m;
    __syncthreads();
    for (int s = 128; s > 0; s >>= 1) {
        if (t < s) red[t] = fmaxf(red[t], red[t + s]);
        __syncthreads();
    }
    m = red[0];
    __syncthreads();

    float sum = 0.f;
    for (int i = t; i < n; i += 256) {
        float e = __expf(row[i] - m);
        row[i] = e;
        sum += e;
    }
    red[t] = sum;
    __syncthreads();
    for (int s = 128; s > 0; s >>= 1) {
        if (t < s) red[t] += red[t + s];
        __syncthreads();
    }
    float inv = 1.0f / red[0];
    __syncthreads();
    for (int i = t; i < n; i += 256) row[i] *= inv;
}

// --------------------------------------------------------------------------
extern "C" void kernel_launch(void* const* d_in, const int* in_sizes, int n_in,
                              void* d_out, int out_size) {
    const float* query = (const float*)d_in[0];
    const float* key_  = (const float*)d_in[1];
    const float* value = (const float*)d_in[2];
    const float* Qw = (const float*)d_in[3];
    const float* Kw = (const float*)d_in[4];
    const float* Vw = (const float*)d_in[5];
    const float* QA = (const float*)d_in[6];
    const float* QB = (const float*)d_in[7];
    const float* KA = (const float*)d_in[8];
    const float* KB = (const float*)d_in[9];
    const float* VA = (const float*)d_in[10];
    const float* VB = (const float*)d_in[11];
    const float* Ow = (const float*)d_in[12];
    float* out = (float*)d_out;

    float *weff, *q, *k, *vT, *scores, *ctx;
    cudaGetSymbolAddress((void**)&weff, g_weff);
    cudaGetSymbolAddress((void**)&q, g_q);
    cudaGetSymbolAddress((void**)&k, g_k);
    cudaGetSymbolAddress((void**)&vT, g_vT);
    cudaGetSymbolAddress((void**)&scores, g_scores);
    cudaGetSymbolAddress((void**)&ctx, g_ctx);
    float* weff_q = weff;
    float* weff_k = weff + (size_t)EDIM * EDIM;
    float* weff_v = weff + (size_t)2 * EDIM * EDIM;

    cudaFuncSetAttribute(gemm_tc_kernel, cudaFuncAttributeMaxDynamicSharedMemorySize, GEMM_SMEM);

    // 1) fold LoRA into effective weights (one launch, grid.z = 3)
    dim3 gf(EDIM * EDIM / 256, 1, 3);
    fold_lora_kernel<<<gf, 256>>>(Qw, QB, QA, Kw, KB, KA, Vw, VB, VA, weff);

    // 2) projections: [8192,1024] @ Weff^T  (V written transposed -> vT[E][MTOT])
    dim3 gp(EDIM / BN, MTOT / BM, 1);
    gemm_tc_kernel<<<gp, 256, GEMM_SMEM>>>(query, weff_q, q, EDIM, EDIM, EDIM, EDIM, 1.f, 0, 0, 0, 0);
    gemm_tc_kernel<<<gp, 256, GEMM_SMEM>>>(key_,  weff_k, k, EDIM, EDIM, EDIM, EDIM, 1.f, 0, 0, 0, 0);
    gemm_tc_kernel<<<gp, 256, GEMM_SMEM>>>(value, weff_v, vT, EDIM, EDIM, MTOT, EDIM, 1.f, 1, 0, 0, 0);

    // 3) scores[b] = Q[b] @ K[b]^T / 32
    dim3 gs(SLEN / BN, SLEN / BM, BATCH);
    gemm_tc_kernel<<<gs, 256, GEMM_SMEM>>>(q, k, scores, EDIM, EDIM, SLEN, EDIM, 0.03125f, 0,
                                           (long)SLEN * EDIM, (long)SLEN * EDIM, (long)SLEN * SLEN);

    // 4) row softmax
    softmax_rows_kernel<<<BATCH * SLEN, 256>>>(scores, SLEN);

    // 5) ctx[b] = attn[b] @ V[b] == attn[b] @ (vT[:, b*S:(b+1)*S])^T  (NT form)
    dim3 gc(EDIM / BN, SLEN / BM, BATCH);
    gemm_tc_kernel<<<gc, 256, GEMM_SMEM>>>(scores, vT, ctx, SLEN, MTOT, EDIM, SLEN, 1.f, 0,
                                           (long)SLEN * SLEN, (long)SLEN, (long)SLEN * EDIM);

    // 6) out = ctx @ O^T
    dim3 go(EDIM / BN, MTOT / BM, 1);
    gemm_tc_kernel<<<go, 256, GEMM_SMEM>>>(ctx, Ow, out, EDIM, EDIM, EDIM, EDIM, 1.f, 0, 0, 0, 0);
}

// round 8
// speedup vs baseline: 3.3979x; 1.0772x over previous
#include <cuda_runtime.h>
#include <cstdint>

// Problem dims (fixed by the reference)
#define EDIM 1024
#define RDIM 16
#define BATCH 4
#define SLEN 2048
#define MTOT (BATCH * SLEN)   // 8192

// ---------------- device scratch (no allocations allowed) ----------------
__device__ float g_weff[3][EDIM * EDIM];                 // Q,K,V effective weights (tf32)
__device__ float g_xq[(size_t)MTOT * EDIM];              // tf32 copies of inputs
__device__ float g_xk[(size_t)MTOT * EDIM];
__device__ float g_xv[(size_t)MTOT * EDIM];
__device__ float g_ow[EDIM * EDIM];
__device__ float g_q[(size_t)MTOT * EDIM];
__device__ float g_k[(size_t)MTOT * EDIM];
__device__ float g_vT[(size_t)EDIM * MTOT];              // V projection, transposed
__device__ float g_scores[(size_t)BATCH * SLEN * SLEN];
__device__ float g_ctx[(size_t)MTOT * EDIM];

__device__ __forceinline__ float rtf(float f) {          // round-to-nearest tf32, as fp32 bits
    uint32_t u;
    asm("cvt.rna.tf32.f32 %0, %1;" : "=r"(u) : "f"(f));
    return __uint_as_float(u);
}

// ---- elementwise tf32 rounding copy (float4 granularity) ----
__global__ void round_tf32_kernel(const float4* __restrict__ src, float4* __restrict__ dst) {
    size_t i = (size_t)blockIdx.x * blockDim.x + threadIdx.x;
    float4 v = src[i];
    v.x = rtf(v.x); v.y = rtf(v.y); v.z = rtf(v.z); v.w = rtf(v.w);
    dst[i] = v;
}

// ---- fold LoRA: Weff[f][e] = tf32(W[f][e] + sum_r B[f][r]*A[r][e]) ----
__global__ void fold_lora_kernel(const float* __restrict__ W0, const float* __restrict__ B0,
                                 const float* __restrict__ A0,
                                 const float* __restrict__ W1, const float* __restrict__ B1,
                                 const float* __restrict__ A1,
                                 const float* __restrict__ W2, const float* __restrict__ B2,
                                 const float* __restrict__ A2,
                                 float* __restrict__ Weff) {
    const float *W, *Bm, *Am;
    if (blockIdx.z == 0)      { W = W0; Bm = B0; Am = A0; }
    else if (blockIdx.z == 1) { W = W1; Bm = B1; Am = A1; }
    else                      { W = W2; Bm = B2; Am = A2; }
    float* dst = Weff + (size_t)blockIdx.z * EDIM * EDIM;
    int idx = blockIdx.x * blockDim.x + threadIdx.x;
    int f = idx >> 10;
    int e = idx & (EDIM - 1);
    float acc = W[idx];
#pragma unroll
    for (int r = 0; r < RDIM; r++) acc += Bm[f * RDIM + r] * Am[r * EDIM + e];
    dst[idx] = rtf(acc);
}

// ======== tf32 mma.sync NT GEMM: C[m][n] = alpha * sum_k A[m][k]*B[n][k] ========
// Inputs MUST already be tf32-rounded in memory (low mantissa bits zero) — the
// inner loop feeds raw fp32 bits to mma.sync with no per-fragment cvt.
// Block tile 128x128x32, 8 warps (2 x 4), warp tile 64x32, mma m16n8k8.
#define BM 128
#define BN 128
#define BK 32
#define SMSTRIDE 36                         // floats per row (32 + 4 pad) -> conflict-free frags
#define TILE_F (128 * SMSTRIDE)
#define STAGE_F (2 * TILE_F)
#define GEMM_SMEM (2 * STAGE_F * 4)         // 2 stages, 73728 bytes

__device__ __forceinline__ void mma_tf32(float c[4], const uint32_t a[4], const uint32_t b[2]) {
    asm volatile(
        "mma.sync.aligned.m16n8k8.row.col.f32.tf32.tf32.f32 "
        "{%0,%1,%2,%3}, {%4,%5,%6,%7}, {%8,%9}, {%0,%1,%2,%3};"
        : "+f"(c[0]), "+f"(c[1]), "+f"(c[2]), "+f"(c[3])
        : "r"(a[0]), "r"(a[1]), "r"(a[2]), "r"(a[3]), "r"(b[0]), "r"(b[1]));
}

__global__ __launch_bounds__(256) void gemm_tc_kernel(
    const float* __restrict__ A, const float* __restrict__ B, float* __restrict__ C,
    int ldA, int ldB, int ldC, int Kdim, float alpha, int transC, int roundC,
    long sA, long sB, long sC) {
    extern __shared__ __align__(16) float sm[];
    A += (size_t)blockIdx.z * sA + (size_t)blockIdx.y * BM * ldA;
    B += (size_t)blockIdx.z * sB + (size_t)blockIdx.x * BN * ldB;
    C += (size_t)blockIdx.z * sC;
    const int tid = threadIdx.x;
    const int wid = tid >> 5, lid = tid & 31;
    const int wm = wid & 1, wn = wid >> 1;      // warp grid 2 x 4
    const int mb = wm * 64, nb = wn * 32;
    const int g = lid >> 2, t = lid & 3;

    float acc[4][4][4];
#pragma unroll
    for (int im = 0; im < 4; im++)
#pragma unroll
        for (int in = 0; in < 4; in++)
#pragma unroll
            for (int q = 0; q < 4; q++) acc[im][in][q] = 0.f;

    const int NT = Kdim / BK;

#define LOAD_TILE(KT, S)                                                          \
    do {                                                                          \
        float* as = sm + (S) * STAGE_F;                                           \
        float* bs = as + TILE_F;                                                  \
        const float* Ag = A + (size_t)(KT) * BK;                                  \
        const float* Bg = B + (size_t)(KT) * BK;                                  \
        _Pragma("unroll")                                                         \
        for (int j = 0; j < 4; j++) {                                             \
            int idx = j * 256 + tid;                                              \
            int r = idx >> 3, q = idx & 7;                                        \
            uint32_t so;                                                          \
            asm("{ .reg .u64 u; cvta.to.shared.u64 u, %1; cvt.u32.u64 %0, u; }"   \
                : "=r"(so) : "l"(as + r * SMSTRIDE + q * 4));                     \
            asm volatile("cp.async.cg.shared.global [%0], [%1], 16;"              \
                         :: "r"(so), "l"(Ag + (size_t)r * ldA + q * 4));          \
        }                                                                         \
        _Pragma("unroll")                                                         \
        for (int j = 0; j < 4; j++) {                                             \
            int idx = j * 256 + tid;                                              \
            int r = idx >> 3, q = idx & 7;                                        \
            uint32_t so;                                                          \
            asm("{ .reg .u64 u; cvta.to.shared.u64 u, %1; cvt.u32.u64 %0, u; }"   \
                : "=r"(so) : "l"(bs + r * SMSTRIDE + q * 4));                     \
            asm volatile("cp.async.cg.shared.global [%0], [%1], 16;"              \
                         :: "r"(so), "l"(Bg + (size_t)r * ldB + q * 4));          \
        }                                                                         \
        asm volatile("cp.async.commit_group;" ::: "memory");                      \
    } while (0)

    LOAD_TILE(0, 0);
    if (NT > 1) LOAD_TILE(1, 1);

    for (int kt = 0; kt < NT; kt++) {
        if (kt + 1 < NT)
            asm volatile("cp.async.wait_group 1;" ::: "memory");
        else
            asm volatile("cp.async.wait_group 0;" ::: "memory");
        __syncthreads();

        const float* as = sm + (kt & 1) * STAGE_F;
        const float* bs = as + TILE_F;
#pragma unroll
        for (int ks = 0; ks < 4; ks++) {
            const int k0 = ks * 8;
            uint32_t ua[4][4];
#pragma unroll
            for (int im = 0; im < 4; im++) {
                const float* ap = as + (mb + im * 16 + g) * SMSTRIDE + k0 + t;
                ua[im][0] = __float_as_uint(ap[0]);
                ua[im][1] = __float_as_uint(ap[8 * SMSTRIDE]);
                ua[im][2] = __float_as_uint(ap[4]);
                ua[im][3] = __float_as_uint(ap[8 * SMSTRIDE + 4]);
            }
            uint32_t ub[4][2];
#pragma unroll
            for (int in = 0; in < 4; in++) {
                const float* bp = bs + (nb + in * 8 + g) * SMSTRIDE + k0 + t;
                ub[in][0] = __float_as_uint(bp[0]);
                ub[in][1] = __float_as_uint(bp[4]);
            }
#pragma unroll
            for (int im = 0; im < 4; im++)
#pragma unroll
                for (int in = 0; in < 4; in++) mma_tf32(acc[im][in], ua[im], ub[in]);
        }
        __syncthreads();
        if (kt + 2 < NT) LOAD_TILE(kt + 2, kt & 1);
    }

    // epilogue (optionally tf32-round outputs that feed later GEMMs)
#pragma unroll
    for (int im = 0; im < 4; im++) {
        const int row0 = blockIdx.y * BM + mb + im * 16 + g;
#pragma unroll
        for (int in = 0; in < 4; in++) {
            const int col = blockIdx.x * BN + nb + in * 8 + t * 2;
            float v0 = acc[im][in][0] * alpha, v1 = acc[im][in][1] * alpha;
            float v2 = acc[im][in][2] * alpha, v3 = acc[im][in][3] * alpha;
            if (roundC) { v0 = rtf(v0); v1 = rtf(v1); v2 = rtf(v2); v3 = rtf(v3); }
            if (!transC) {
                *reinterpret_cast<float2*>(&C[(size_t)row0 * ldC + col]) = make_float2(v0, v1);
                *reinterpret_cast<float2*>(&C[(size_t)(row0 + 8) * ldC + col]) = make_float2(v2, v3);
            } else {
                C[(size_t)col * ldC + row0] = v0;
                C[(size_t)(col + 1) * ldC + row0] = v1;
                C[(size_t)col * ldC + row0 + 8] = v2;
                C[(size_t)(col + 1) * ldC + row0 + 8] = v3;
            }
        }
    }
}

// ---------------- row softmax, output rounded to tf32 ----------------------
__global__ void softmax_rows_kernel(float* __restrict__ Sc, int n) {
    float* row = Sc + (size_t)blockIdx.x * n;
    __shared__ float red[256];
    const int t = threadIdx.x;

    float m = -3.4e38f;
    for (int i = t; i < n; i += 256) m = fmaxf(m, row[i]);
    red[t] = m;
    __syncthreads();
    for (int s = 128; s > 0; s >>= 1) {
        if (t < s) red[t] = fmaxf(red[t], red[t + s]);
        __syncthreads();
    }
    m = red[0];
    __syncthreads();

    float sum = 0.f;
    for (int i = t; i < n; i += 256) {
        float e = __expf(row[i] - m);
        row[i] = e;
        sum += e;
    }
    red[t] = sum;
    __syncthreads();
    for (int s = 128; s > 0; s >>= 1) {
        if (t < s) red[t] += red[t + s];
        __syncthreads();
    }
    float inv = 1.0f / red[0];
    __syncthreads();
    for (int i = t; i < n; i += 256) row[i] = rtf(row[i] * inv);
}

// --------------------------------------------------------------------------
extern "C" void kernel_launch(void* const* d_in, const int* in_sizes, int n_in,
                              void* d_out, int out_size) {
    const float* query = (const float*)d_in[0];
    const float* key_  = (const float*)d_in[1];
    const float* value = (const float*)d_in[2];
    const float* Qw = (const float*)d_in[3];
    const float* Kw = (const float*)d_in[4];
    const float* Vw = (const float*)d_in[5];
    const float* QA = (const float*)d_in[6];
    const float* QB = (const float*)d_in[7];
    const float* KA = (const float*)d_in[8];
    const float* KB = (const float*)d_in[9];
    const float* VA = (const float*)d_in[10];
    const float* VB = (const float*)d_in[11];
    const float* Ow = (const float*)d_in[12];
    float* out = (float*)d_out;

    float *weff, *xq, *xk, *xv, *ow, *q, *k, *vT, *scores, *ctx;
    cudaGetSymbolAddress((void**)&weff, g_weff);
    cudaGetSymbolAddress((void**)&xq, g_xq);
    cudaGetSymbolAddress((void**)&xk, g_xk);
    cudaGetSymbolAddress((void**)&xv, g_xv);
    cudaGetSymbolAddress((void**)&ow, g_ow);
    cudaGetSymbolAddress((void**)&q, g_q);
    cudaGetSymbolAddress((void**)&k, g_k);
    cudaGetSymbolAddress((void**)&vT, g_vT);
    cudaGetSymbolAddress((void**)&scores, g_scores);
    cudaGetSymbolAddress((void**)&ctx, g_ctx);
    float* weff_q = weff;
    float* weff_k = weff + (size_t)EDIM * EDIM;
    float* weff_v = weff + (size_t)2 * EDIM * EDIM;

    cudaFuncSetAttribute(gemm_tc_kernel, cudaFuncAttributeMaxDynamicSharedMemorySize, GEMM_SMEM);

    // 0) tf32-round the raw GEMM inputs into scratch
    const size_t nqkv4 = (size_t)MTOT * EDIM / 4;
    round_tf32_kernel<<<nqkv4 / 256, 256>>>((const float4*)query, (float4*)xq);
    round_tf32_kernel<<<nqkv4 / 256, 256>>>((const float4*)key_,  (float4*)xk);
    round_tf32_kernel<<<nqkv4 / 256, 256>>>((const float4*)value, (float4*)xv);
    round_tf32_kernel<<<(size_t)EDIM * EDIM / 4 / 256, 256>>>((const float4*)Ow, (float4*)ow);

    // 1) fold LoRA into effective weights (tf32-rounded at store)
    dim3 gf(EDIM * EDIM / 256, 1, 3);
    fold_lora_kernel<<<gf, 256>>>(Qw, QB, QA, Kw, KB, KA, Vw, VB, VA, weff);

    // 2) projections: [8192,1024] @ Weff^T  (V written transposed; outputs tf32-rounded)
    dim3 gp(EDIM / BN, MTOT / BM, 1);
    gemm_tc_kernel<<<gp, 256, GEMM_SMEM>>>(xq, weff_q, q, EDIM, EDIM, EDIM, EDIM, 1.f, 0, 1, 0, 0, 0);
    gemm_tc_kernel<<<gp, 256, GEMM_SMEM>>>(xk, weff_k, k, EDIM, EDIM, EDIM, EDIM, 1.f, 0, 1, 0, 0, 0);
    gemm_tc_kernel<<<gp, 256, GEMM_SMEM>>>(xv, weff_v, vT, EDIM, EDIM, MTOT, EDIM, 1.f, 1, 1, 0, 0, 0);

    // 3) scores[b] = Q[b] @ K[b]^T / 32  (not rounded; softmax rounds)
    dim3 gs(SLEN / BN, SLEN / BM, BATCH);
    gemm_tc_kernel<<<gs, 256, GEMM_SMEM>>>(q, k, scores, EDIM, EDIM, SLEN, EDIM, 0.03125f, 0, 0,
                                           (long)SLEN * EDIM, (long)SLEN * EDIM, (long)SLEN * SLEN);

    // 4) row softmax (stores tf32-rounded probabilities)
    softmax_rows_kernel<<<BATCH * SLEN, 256>>>(scores, SLEN);

    // 5) ctx[b] = attn[b] @ V[b] (NT via vT; output rounded for next GEMM)
    dim3 gc(EDIM / BN, SLEN / BM, BATCH);
    gemm_tc_kernel<<<gc, 256, GEMM_SMEM>>>(scores, vT, ctx, SLEN, MTOT, EDIM, SLEN, 1.f, 0, 1,
                                           (long)SLEN * SLEN, (long)SLEN, (long)SLEN * EDIM);

    // 6) out = ctx @ O^T (final output, full fp32)
    dim3 go(EDIM / BN, MTOT / BM, 1);
    gemm_tc_kernel<<<go, 256, GEMM_SMEM>>>(ctx, ow, out, EDIM, EDIM, EDIM, EDIM, 1.f, 0, 0, 0, 0, 0);
}